// round 15
// baseline (speedup 1.0000x reference)
#include <cuda_runtime.h>
#include <cuda_bf16.h>
#include <cuda_fp16.h>
#include <math.h>
#include <stdint.h>

#define BATCH 64
#define SEQ   512
#define HID   1024
#define LRI   (0.01f / 1024.0f)
#define EPS_  1e-5f
#define CHUNK 64
#define NCHUNK (SEQ / CHUNK)
#define MTOT (BATCH * SEQ)

// ---------------- device scratch ----------------
__device__ __half g_xh[(size_t)MTOT * HID];
__device__ __half g_ach[(size_t)MTOT * HID];     // act = silu(err+T) fp16
__device__ __half g_tth[(size_t)MTOT * HID];     // ttt fp16
__device__ __half g_Ch[(size_t)BATCH * SEQ * SEQ];   // Chat fp16
__device__ __half g_wd[HID * HID];
__device__ __half g_wt[HID * HID];
__device__ __half g_wo[HID * HID];
__device__ __half g_wg1[HID * HID];
__device__ __half g_wg2[HID * HID];
__device__ float g_dbias[HID];
__device__ float g_D[(size_t)MTOT * HID];   // D, later z
__device__ float g_T[(size_t)MTOT * HID];   // target
__device__ float g_TTT[(size_t)MTOT * HID]; // ttt fp32

// ---------------- PTX helpers (plain sm_80+ features only) ----------------
static __device__ __forceinline__ uint32_t s2u(const void* p) {
    uint32_t a;
    asm("{ .reg .u64 t; cvta.to.shared.u64 t, %1; cvt.u32.u64 %0, t; }" : "=r"(a) : "l"(p));
    return a;
}
#define CPA(dst, src) \
    asm volatile("cp.async.cg.shared.global [%0], [%1], 16;" :: "r"(dst), "l"(src))
#define CPCOMMIT() asm volatile("cp.async.commit_group;" ::: "memory")
#define CPWAIT1()  asm volatile("cp.async.wait_group 1;" ::: "memory")
#define LDSM4(r, addr) \
    asm volatile("ldmatrix.sync.aligned.m8n8.x4.shared.b16 {%0,%1,%2,%3}, [%4];" \
                 : "=r"((r)[0]), "=r"((r)[1]), "=r"((r)[2]), "=r"((r)[3]) : "r"(addr))
#define MMA(c, a, b0, b1) \
    asm volatile("mma.sync.aligned.m16n8k16.row.col.f32.f16.f16.f32 " \
                 "{%0,%1,%2,%3}, {%4,%5,%6,%7}, {%8,%9}, {%0,%1,%2,%3};" \
                 : "+f"((c)[0]), "+f"((c)[1]), "+f"((c)[2]), "+f"((c)[3]) \
                 : "r"((a)[0]), "r"((a)[1]), "r"((a)[2]), "r"((a)[3]), "r"(b0), "r"(b1))

#define BUF_BYTES 10240
#define STG_BYTES (2 * BUF_BYTES)
#define SMEM_BYTES (3 * STG_BYTES)

// ---------------- tensor GEMM: C[m][n] = sum_k A[m][k]*B[n][k] -------------
// mode 0: C = v + bias (K2>0: dual-K source A2/B2 continues accumulation)
// mode 1: gram, Coh = fp16(LRI*(v+1)), skip upper tiles, batched via bz
// mode 2: dual-N: tiles with n0>=HID use weight2 (B2h), bias2, C2
__global__ __launch_bounds__(256, 1)
void tgemm(const __half* __restrict__ Ah, const __half* __restrict__ Bh,
           const __half* __restrict__ A2h, const __half* __restrict__ B2h,
           const float* __restrict__ bias, float* __restrict__ C,
           const float* __restrict__ bias2, float* __restrict__ C2,
           int lda, int ldb, int ldc,
           long long sA, long long sB, long long sC,
           int K1, int K2, int mode,
           __half* __restrict__ Coh) {
    if (mode == 1 && blockIdx.x > blockIdx.y) return;
    extern __shared__ char smem[];
    const uint32_t su = s2u(smem);
    const int tid = threadIdx.x;
    const int wid = tid >> 5, lane = tid & 31;
    const int wm = wid >> 2, wn = wid & 3;          // 2 x 4 warp grid, 64x32 per warp
    const int m0 = blockIdx.y * 128;
    int n0 = blockIdx.x * 128;
    const size_t bz = blockIdx.z;

    const float* biasSel = bias;
    float* Csel = C;
    if (mode == 2 && n0 >= HID) { n0 -= HID; Bh = B2h; biasSel = bias2; Csel = C2; }

    const __half* aH = Ah + bz * sA + (size_t)m0 * lda;
    const __half* bH = Bh + bz * sB + (size_t)n0 * ldb;
    const __half *a2H = nullptr, *b2H = nullptr;
    if (K2) {
        a2H = A2h + (size_t)m0 * lda;
        b2H = B2h + (size_t)n0 * ldb;
    }
    const int nc1 = K1 >> 5;
    const int NC = nc1 + (K2 >> 5);

    uint32_t aoff[4], boff[2];
#pragma unroll
    for (int mi = 0; mi < 4; mi++)
        aoff[mi] = (uint32_t)((wm * 64 + mi * 16 + (lane & 7) + ((lane >> 3) & 1) * 8) * 80
                              + ((lane >> 4) & 1) * 16);
#pragma unroll
    for (int g = 0; g < 2; g++)
        boff[g] = (uint32_t)((wn * 32 + g * 16 + (lane & 7) + ((lane >> 4) & 1) * 8) * 80
                             + ((lane >> 3) & 1) * 16);

    float acc[4][4][4];
#pragma unroll
    for (int i = 0; i < 4; i++)
#pragma unroll
        for (int j = 0; j < 4; j++)
#pragma unroll
            for (int r = 0; r < 4; r++) acc[i][j][r] = 0.f;

    auto load_chunk = [&](int stage, int c) {
        const __half *s0, *s1; int k0;
        if (c < nc1) { s0 = aH; s1 = bH; k0 = c << 5; }
        else         { s0 = a2H; s1 = b2H; k0 = (c - nc1) << 5; }
        const __half* srcs[2] = { s0, s1 };
        const int lds[2] = { lda, ldb };
        const uint32_t d0 = su + stage * STG_BYTES;
#pragma unroll
        for (int it = 0; it < 4; it++) {
            int t = it * 256 + tid;
            int buf = t >> 9, w = t & 511, row = w >> 2, ch = w & 3;
            const __half* g = srcs[buf] + (size_t)row * lds[buf] + k0 + ch * 8;
            CPA(d0 + buf * BUF_BYTES + row * 80 + ch * 16, g);
        }
    };

    load_chunk(0, 0); CPCOMMIT();
    if (NC > 1) load_chunk(1, 1);
    CPCOMMIT();

    for (int c = 0; c < NC; c++) {
        CPWAIT1();
        __syncthreads();
        if (c + 2 < NC) load_chunk((c + 2) % 3, c + 2);
        CPCOMMIT();

        const uint32_t sb0 = su + (c % 3) * STG_BYTES;
#pragma unroll
        for (int kk = 0; kk < 2; kk++) {
            uint32_t ahf[4][4], bhf[2][4];
#pragma unroll
            for (int mi = 0; mi < 4; mi++)
                LDSM4(ahf[mi], sb0 + aoff[mi] + kk * 32);
#pragma unroll
            for (int g = 0; g < 2; g++)
                LDSM4(bhf[g], sb0 + BUF_BYTES + boff[g] + kk * 32);
#pragma unroll
            for (int mi = 0; mi < 4; mi++)
#pragma unroll
                for (int nj = 0; nj < 4; nj++) {
                    const int g = nj >> 1, h = (nj & 1) * 2;
                    MMA(acc[mi][nj], ahf[mi], bhf[g][h], bhf[g][h + 1]);
                }
        }
    }

    // epilogue
    float* Cb = Csel ? Csel + bz * sC : nullptr;
    __half* Cho = Coh ? Coh + bz * sC : nullptr;
    const int g4 = lane >> 2, tg = (lane & 3) * 2;
#pragma unroll
    for (int mi = 0; mi < 4; mi++)
#pragma unroll
        for (int nj = 0; nj < 4; nj++) {
            const int col = n0 + wn * 32 + nj * 8 + tg;
            float bv0 = 0.f, bv1 = 0.f;
            if (mode != 1 && biasSel) { bv0 = biasSel[col]; bv1 = biasSel[col + 1]; }
#pragma unroll
            for (int half_ = 0; half_ < 2; half_++) {
                const int row = m0 + wm * 64 + mi * 16 + g4 + half_ * 8;
                float v0 = acc[mi][nj][half_ * 2], v1 = acc[mi][nj][half_ * 2 + 1];
                const size_t gi = (size_t)row * ldc + col;
                if (mode == 1) {
                    v0 = LRI * (v0 + 1.f); v1 = LRI * (v1 + 1.f);
                    __half2 hp; hp.x = __float2half_rn(v0); hp.y = __float2half_rn(v1);
                    *(__half2*)&Cho[gi] = hp;
                } else {
                    v0 += bv0; v1 += bv1;
                    *(float2*)&Cb[gi] = make_float2(v0, v1);
                    if (Cho) {
                        __half2 hp; hp.x = __float2half_rn(v0); hp.y = __float2half_rn(v1);
                        *(__half2*)&Cho[gi] = hp;
                    }
                }
            }
        }
}

// ---------------- prep kernels ----------------
// z selects one of 5 weight conversions: transpose fp32 [K][N] -> fp16 [N][K]
__global__ void wconv5(const float* __restrict__ Wi, const float* __restrict__ Wt,
                       const float* __restrict__ Wo, const float* __restrict__ Wg,
                       __half* __restrict__ od, __half* __restrict__ ot,
                       __half* __restrict__ oo, __half* __restrict__ og1,
                       __half* __restrict__ og2) {
    __shared__ float t[32][33];
    const float* W; const float* Wsub = nullptr; __half* oh;
    switch (blockIdx.z) {
        case 0: W = Wi; Wsub = Wt; oh = od; break;
        case 1: W = Wt; oh = ot; break;
        case 2: W = Wo; oh = oo; break;
        case 3: W = Wg; oh = og1; break;
        default: W = Wg + (size_t)HID * HID; oh = og2; break;
    }
    int bx = blockIdx.x * 32, by = blockIdx.y * 32;
    int tx = threadIdx.x, ty = threadIdx.y;
    for (int i = ty; i < 32; i += 8) {
        float v = W[(size_t)(by + i) * HID + bx + tx];
        if (Wsub) v -= Wsub[(size_t)(by + i) * HID + bx + tx];
        t[i][tx] = v;
    }
    __syncthreads();
    for (int i = ty; i < 32; i += 8)
        oh[(size_t)(bx + i) * HID + by + tx] = __float2half_rn(t[tx][i]);
}

__global__ void cvt_h(const float* __restrict__ in, __half* __restrict__ oh) {
    size_t i = ((size_t)blockIdx.x * blockDim.x + threadIdx.x) * 2;
    float2 v = *(const float2*)&in[i];
    __half2 h; h.x = __float2half_rn(v.x); h.y = __float2half_rn(v.y);
    *(__half2*)&oh[i] = h;
}

__global__ void dbias_k(const float* __restrict__ bi, const float* __restrict__ bt) {
    int i = blockIdx.x * 256 + threadIdx.x;
    if (i < HID) g_dbias[i] = bi[i] - bt[i];
}

// ---------------- fused solve: all 8 chunks in one launch ------------------
// One block per (i-block of 128 cols, batch). errT lives entirely in smem.
// Per chunk q: history corr via mma against smem errT, fp32 diag recurrence,
// fused silu epilogue writing act fp16; err written back to smem errT only.
// smem layout (bytes):
//   errT: [128][520] fp16                0      .. 133120
//   sA  : [64][72]  fp16 (C tile)        133120 .. 142336
//   sDg : [64][65]  fp32 (diag C)        142336 .. 158976
//   corr: [64][132] fp32                 158976 .. 192768
#define SOLVE_SMEM 192768
__global__ __launch_bounds__(128, 1)
void solve_fused() {
    extern __shared__ char sm[];
    const int b = blockIdx.y;
    const int i0 = blockIdx.x * 128;
    const int tid = threadIdx.x;
    const int wid = tid >> 5, lane = tid & 31;

    __half* errT = (__half*)sm;
    __half* sA   = (__half*)(sm + 133120);
    float* sDg   = (float*)(sm + 142336);
    float* corr  = (float*)(sm + 158976);
    const uint32_t suA = s2u(sA);
    const uint32_t suE = s2u(errT);

    const __half* Ch = g_Ch + (size_t)b * SEQ * SEQ;
    const float* Drow = g_D + (size_t)b * SEQ * HID + i0 + tid;
    const float* Trow = g_T + (size_t)b * SEQ * HID + i0 + tid;
    __half* arow = g_ach + (size_t)b * SEQ * HID + i0 + tid;

    uint32_t aoff[4], boff[2];
#pragma unroll
    for (int mi = 0; mi < 4; mi++)
        aoff[mi] = (uint32_t)((mi * 16 + (lane & 7) + ((lane >> 3) & 1) * 8) * 144
                              + ((lane >> 4) & 1) * 16);
#pragma unroll
    for (int g = 0; g < 2; g++)
        boff[g] = (uint32_t)((wid * 32 + g * 16 + (lane & 7) + ((lane >> 4) & 1) * 8) * 1040
                             + ((lane >> 3) & 1) * 16);

    const int g4 = lane >> 2, tg = (lane & 3) * 2;

    for (int q = 0; q < NCHUNK; q++) {
        const int t0 = q * CHUNK;

        float acc[4][4][4];
#pragma unroll
        for (int mi = 0; mi < 4; mi++)
#pragma unroll
            for (int nj = 0; nj < 4; nj++)
#pragma unroll
                for (int r = 0; r < 4; r++) acc[mi][nj][r] = 0.f;

        for (int sb = 0; sb < q; sb++) {
            __syncthreads();   // protect sA (prev reads) and errT (prev writes)
#pragma unroll
            for (int it = 0; it < 4; it++) {
                int c = it * 128 + tid;
                int row = c >> 3, ch = c & 7;
                *(uint4*)(sA + row * 72 + ch * 8) =
                    *(const uint4*)(Ch + (size_t)(t0 + row) * SEQ + sb * 64 + ch * 8);
            }
            __syncthreads();
#pragma unroll
            for (int kk = 0; kk < 4; kk++) {
                uint32_t ahf[4][4], bhf[2][4];
#pragma unroll
                for (int mi = 0; mi < 4; mi++)
                    LDSM4(ahf[mi], suA + aoff[mi] + kk * 32);
#pragma unroll
                for (int g = 0; g < 2; g++)
                    LDSM4(bhf[g], suE + boff[g] + sb * 128 + kk * 32);
#pragma unroll
                for (int mi = 0; mi < 4; mi++)
#pragma unroll
                    for (int nj = 0; nj < 4; nj++) {
                        const int g = nj >> 1, h = (nj & 1) * 2;
                        MMA(acc[mi][nj], ahf[mi], bhf[g][h], bhf[g][h + 1]);
                    }
            }
        }

        // dump correction (fragment -> column layout) + load diag C
        __syncthreads();
#pragma unroll
        for (int mi = 0; mi < 4; mi++)
#pragma unroll
            for (int nj = 0; nj < 4; nj++) {
                const int col = wid * 32 + nj * 8 + tg;
#pragma unroll
                for (int half_ = 0; half_ < 2; half_++) {
                    const int row = mi * 16 + g4 + half_ * 8;
                    corr[row * 132 + col] = acc[mi][nj][half_ * 2];
                    corr[row * 132 + col + 1] = acc[mi][nj][half_ * 2 + 1];
                }
            }
#pragma unroll
        for (int it = 0; it < 32; it++) {
            int c = it * 128 + tid;
            int row = c >> 6, s = c & 63;
            sDg[row * 65 + s] = __half2float(Ch[(size_t)(t0 + row) * SEQ + t0 + s]);
        }
        __syncthreads();

        // fp32 diagonal recurrence
        float e[64];
#pragma unroll
        for (int t = 0; t < 64; t++)
            e[t] = Drow[(size_t)(t0 + t) * HID] - corr[t * 132 + tid];

#pragma unroll
        for (int t = 1; t < 64; t++) {
            float sum = 0.f;
#pragma unroll
            for (int s = 0; s < t; s++) sum += sDg[t * 65 + s] * e[s];
            e[t] -= sum;
        }

        // fused silu epilogue + err writeback to smem
#pragma unroll
        for (int t = 0; t < 64; t++) {
            float inner = e[t] + Trow[(size_t)(t0 + t) * HID];
            float s = inner / (1.0f + expf(-inner));
            arow[(size_t)(t0 + t) * HID] = __float2half_rn(s);
        }
        if (q < NCHUNK - 1) {
#pragma unroll
            for (int t = 0; t < 32; t++) {
                __half2 hp;
                hp.x = __float2half_rn(e[t * 2]);
                hp.y = __float2half_rn(e[t * 2 + 1]);
                *(__half2*)(errT + (size_t)tid * 520 + t0 + t * 2) = hp;
            }
        }
    }
}

// ---------------- gate + mix + layernorm ----------------
__global__ __launch_bounds__(256)
void gate_ln(const float* __restrict__ x, const float* __restrict__ gamma,
             const float* __restrict__ beta, float* __restrict__ out) {
    const size_t row = blockIdx.x;
    const float* zr = g_D + row * HID;
    const float* tr = g_TTT + row * HID;
    const float* xr = x + row * HID;

    float y[4];
    float sum = 0.f, sumsq = 0.f;
#pragma unroll
    for (int k = 0; k < 4; k++) {
        int h = threadIdx.x + k * 256;
        float z = zr[h];
        float g = 1.0f / (1.0f + expf(-z));
        float v = g * tr[h] + (1.0f - g) * xr[h];
        y[k] = v;
        sum += v;
        sumsq += v * v;
    }
    __shared__ float sa[8], sbm[8];
#pragma unroll
    for (int o = 16; o > 0; o >>= 1) {
        sum += __shfl_down_sync(0xffffffffu, sum, o);
        sumsq += __shfl_down_sync(0xffffffffu, sumsq, o);
    }
    int w = threadIdx.x >> 5, l = threadIdx.x & 31;
    if (l == 0) { sa[w] = sum; sbm[w] = sumsq; }
    __syncthreads();
    if (w == 0) {
        float a = (l < 8) ? sa[l] : 0.f;
        float bsum = (l < 8) ? sbm[l] : 0.f;
#pragma unroll
        for (int o = 4; o > 0; o >>= 1) {
            a += __shfl_down_sync(0xffu, a, o);
            bsum += __shfl_down_sync(0xffu, bsum, o);
        }
        if (l == 0) { sa[0] = a; sbm[0] = bsum; }
    }
    __syncthreads();
    float mu = sa[0] * (1.0f / HID);
    float var = sbm[0] * (1.0f / HID) - mu * mu;
    float inv = rsqrtf(var + EPS_);
#pragma unroll
    for (int k = 0; k < 4; k++) {
        int h = threadIdx.x + k * 256;
        out[row * HID + h] = (y[k] - mu) * inv * gamma[h] + beta[h];
    }
}

// ---------------------------------------------------------------------------
#define SYMP(T, p, s) T* p; { void* t_; cudaGetSymbolAddress(&t_, s); p = (T*)t_; }

extern "C" void kernel_launch(void* const* d_in, const int* in_sizes, int n_in,
                              void* d_out, int out_size) {
    const float* x      = (const float*)d_in[0];
    const float* W_init = (const float*)d_in[1];
    const float* b_init = (const float*)d_in[2];
    const float* Wt     = (const float*)d_in[3];
    const float* bt     = (const float*)d_in[4];
    const float* Wo     = (const float*)d_in[5];
    const float* bo     = (const float*)d_in[6];
    const float* Wg     = (const float*)d_in[7];
    const float* bg     = (const float*)d_in[8];
    const float* gamma  = (const float*)d_in[9];
    const float* beta   = (const float*)d_in[10];
    float* out = (float*)d_out;

    SYMP(__half, pxh, g_xh);
    SYMP(__half, pah, g_ach);
    SYMP(__half, pth, g_tth);
    SYMP(__half, pCh, g_Ch);
    SYMP(__half, pwd, g_wd);
    SYMP(__half, pwt, g_wt);
    SYMP(__half, pwo, g_wo);
    SYMP(__half, pwg1, g_wg1);
    SYMP(__half, pwg2, g_wg2);
    SYMP(float, pdb, g_dbias);
    SYMP(float, pD, g_D); SYMP(float, pT, g_T); SYMP(float, pTTT, g_TTT);

    cudaFuncSetAttribute(tgemm, cudaFuncAttributeMaxDynamicSharedMemorySize, SMEM_BYTES);
    cudaFuncSetAttribute(solve_fused, cudaFuncAttributeMaxDynamicSharedMemorySize, SOLVE_SMEM);

    // prep
    wconv5<<<dim3(32, 32, 5), dim3(32, 8)>>>(W_init, Wt, Wo, Wg,
                                             pwd, pwt, pwo, pwg1, pwg2);
    dbias_k<<<4, 256>>>(b_init, bt);
    cvt_h<<<(unsigned)(((size_t)MTOT * HID) / 512), 256>>>(x, pxh);

    // 1+2) merged: D = x@Wd + dbias (cols 0-1023), T = x@Wt + bt (cols 1024-2047)
    tgemm<<<dim3(16, 256, 1), 256, SMEM_BYTES>>>(pxh, pwd, nullptr, pwt, pdb, pD,
                                      bt, pT,
                                      HID, HID, HID, 0, 0, 0, HID, 0, 2, nullptr);
    // 3) Chat = fp16(LRI*(X X^T + 1)) per batch (lower tiles only)
    tgemm<<<dim3(4, 4, BATCH), 256, SMEM_BYTES>>>(pxh, pxh, nullptr, nullptr, nullptr, nullptr,
                                      nullptr, nullptr,
                                      HID, HID, SEQ, (long long)SEQ * HID, (long long)SEQ * HID,
                                      (long long)SEQ * SEQ, HID, 0, 1, pCh);
    // 4) fused solve: one launch, all chunks, errT smem-resident
    solve_fused<<<dim3(HID / 128, BATCH), 128, SOLVE_SMEM>>>();
    // 5) ttt = act @ Wo + bo (fp32 + fp16 copy)
    tgemm<<<dim3(8, 256, 1), 256, SMEM_BYTES>>>(pah, pwo, nullptr, nullptr, bo, pTTT,
                                      nullptr, nullptr,
                                      HID, HID, HID, 0, 0, 0, HID, 0, 0, pth);
    // 6) z = x @ Wg_top + ttt @ Wg_bot + bg (dual-K, K=2048)
    tgemm<<<dim3(8, 256, 1), 256, SMEM_BYTES>>>(pxh, pwg1, pth, pwg2, bg, pD,
                                      nullptr, nullptr,
                                      HID, HID, HID, 0, 0, 0, HID, HID, 0, nullptr);
    // 7) gate mix + layernorm
    gate_ln<<<MTOT, 256>>>(x, gamma, beta, out);
}